// round 15
// baseline (speedup 1.0000x reference)
#include <cuda_runtime.h>
#include <cuda_fp16.h>
#include <math_constants.h>

#define N_POINTS 50000
#define CHANNELS 64
#define NREP 4                 // cursor replicas (4x less same-address atomic contention)
#define CAP_SUB 32             // per-replica capacity (~Poisson(8) entries)
#define CAP (NREP * CAP_SUB)   // 128 slots per point row (u16 -> 256B)
#define OVF_CAP (1 << 20)      // overflow list capacity (expected usage: 0)

// Static scratch (no allocations). All __device__ globals are zero-initialized
// at module load; segmax_kernel restores cursors AND consumed bucket slots to
// zero after use, so the invariants (cursors zero, bucket zero = empty
// sentinel) hold for every call and graph replay.
// Replica cursors in SEPARATE arrays -> a point's 4 counters hit different L2
// slices. Bucket slots are stride-4 interleaved: replica r, position k lives
// at slot 4k+r, so K3 consumes ONE contiguous stream (no loop fragmentation).
// Stored value = source_index + 1 (0 = empty/hole sentinel; 50000+1 < 65536).
__device__ int d_cursor0[N_POINTS];
__device__ int d_cursor1[N_POINTS];
__device__ int d_cursor2[N_POINTS];
__device__ int d_cursor3[N_POINTS];
__device__ unsigned short d_bucket[N_POINTS * CAP]; // 12.8 MB
__device__ __half d_feat_h[N_POINTS * CHANNELS];    // 6.4 MB fp16 feature mirror
__device__ int d_ovf_count;
__device__ int d_ovf_list[OVF_CAP];
__device__ int d_done;                              // K3 block-arrival counter

__device__ __forceinline__ int* cursor_ptr(int r, int p) {
    switch (r & 3) {
        case 0:  return &d_cursor0[p];
        case 1:  return &d_cursor1[p];
        case 2:  return &d_cursor2[p];
        default: return &d_cursor3[p];
    }
}

// ---------------------------------------------------------------------------
// K2: bucket-build (1 edge/thread) with privatized, stride-interleaved
// cursors + fused fp32->fp16 feature conversion.
// ---------------------------------------------------------------------------
#define CONV_TASKS (N_POINTS * 8)   // 400000 tasks x 8 floats

__global__ void bucket_kernel(const int* __restrict__ idx,
                              const float* __restrict__ feat,
                              int n_edges) {
    int t = blockIdx.x * blockDim.x + threadIdx.x;

    if (t < CONV_TASKS) {
        const float4* src = reinterpret_cast<const float4*>(feat) + 2 * t;
        float4 a = __ldg(src);
        float4 b = __ldg(src + 1);
        uint4 h;
        *reinterpret_cast<__half2*>(&h.x) = __floats2half2_rn(a.x, a.y);
        *reinterpret_cast<__half2*>(&h.y) = __floats2half2_rn(a.z, a.w);
        *reinterpret_cast<__half2*>(&h.z) = __floats2half2_rn(b.x, b.y);
        *reinterpret_cast<__half2*>(&h.w) = __floats2half2_rn(b.z, b.w);
        *(reinterpret_cast<uint4*>(d_feat_h) + t) = h;
    }

    if (t < n_edges) {
        int2 pr = __ldg(reinterpret_cast<const int2*>(idx) + t);
        int r = t & 3;
        int pos = atomicAdd(cursor_ptr(r, pr.x), 1);
        if (pos < CAP_SUB) {
            d_bucket[pr.x * CAP + 4 * pos + r] = (unsigned short)(pr.y + 1);
        } else {
            int op = atomicAdd(&d_ovf_count, 1);
            if (op < OVF_CAP) d_ovf_list[op] = t;
        }
    }
}

// ---------------------------------------------------------------------------
// K3: dense segment-max on the fp16 mirror. 8 lanes per point, 8 channels
// (16B of halves) per lane; ONE contiguous loop over 4*max(c_r) interleaved
// slots; 8 u16 indices per 16B load -> 8 independent gathers in flight.
// Hole slots (value 0) substitute a known-valid index (max-idempotent;
// duplicate gathers L1-merge). Write-only fp32 store (covers empty segments
// -> -inf). Overflow edges (expected: none) folded via the compact list.
// Epilogue restores zeros: consumed bucket quads, replica cursors, counters.
// ---------------------------------------------------------------------------
#define K3_BLOCK 128
static_assert((N_POINTS * 8) % K3_BLOCK == 0, "grid must be exact");
static_assert(CAP % 8 == 0, "quads must stay inside the row");

__device__ __forceinline__ __half2 hmax4(__half2 a, __half2 b, __half2 c, __half2 d) {
    return __hmax2(__hmax2(a, b), __hmax2(c, d));
}

__global__ void __launch_bounds__(K3_BLOCK)
segmax_kernel(const int* __restrict__ idx, float* __restrict__ out) {
    int t = blockIdx.x * blockDim.x + threadIdx.x;
    int p = t >> 3;
    int c8 = (t & 7) << 3;          // 8 channels per lane

    int c0 = d_cursor0[p], c1 = d_cursor1[p], c2 = d_cursor2[p], c3 = d_cursor3[p];
    bool overflowed = (c0 > CAP_SUB) | (c1 > CAP_SUB) | (c2 > CAP_SUB) | (c3 > CAP_SUB);
    if (c0 > CAP_SUB) c0 = CAP_SUB;
    if (c1 > CAP_SUB) c1 = CAP_SUB;
    if (c2 > CAP_SUB) c2 = CAP_SUB;
    if (c3 > CAP_SUB) c3 = CAP_SUB;
    int cmax = max(max(c0, c1), max(c2, c3));
    int n = 4 * cmax;               // contiguous slots to scan (holes = 0)

    const unsigned short* bkt = d_bucket + p * CAP;        // 256B-aligned row
    // Stored values are index+1: fold the -1 into the feature base pointer.
    const __half* fhm = d_feat_h + c8 - CHANNELS;

    const __half2 ninf = __float2half2_rn(-CUDART_INF_F);
    __half2 m0 = ninf, m1 = ninf, m2 = ninf, m3 = ninf;

    if (n > 0) {
        // Known-valid substitute index: among slots 0..3 (position 0 of each
        // replica) the argmax replica's slot is nonzero since cmax >= 1.
        uint2 f4 = *reinterpret_cast<const uint2*>(bkt);
        int e0 = f4.x & 0xFFFF, e1 = f4.x >> 16;
        int e2 = f4.y & 0xFFFF, e3 = f4.y >> 16;
        int sv = e0 ? e0 : (e1 ? e1 : (e2 ? e2 : e3));

        for (int i = 0; i < n; i += 8) {
            uint4 q = __ldg(reinterpret_cast<const uint4*>(bkt + i));
            int s0 = q.x & 0xFFFF, s1 = q.x >> 16;
            int s2 = q.y & 0xFFFF, s3 = q.y >> 16;
            int s4 = q.z & 0xFFFF, s5 = q.z >> 16;
            int s6 = q.w & 0xFFFF, s7 = q.w >> 16;
            s0 = s0 ? s0 : sv;  s1 = s1 ? s1 : sv;
            s2 = s2 ? s2 : sv;  s3 = s3 ? s3 : sv;
            s4 = s4 ? s4 : sv;  s5 = s5 ? s5 : sv;
            s6 = s6 ? s6 : sv;  s7 = s7 ? s7 : sv;

            uint4 v0 = *reinterpret_cast<const uint4*>(fhm + s0 * CHANNELS);
            uint4 v1 = *reinterpret_cast<const uint4*>(fhm + s1 * CHANNELS);
            uint4 v2 = *reinterpret_cast<const uint4*>(fhm + s2 * CHANNELS);
            uint4 v3 = *reinterpret_cast<const uint4*>(fhm + s3 * CHANNELS);
            uint4 v4 = *reinterpret_cast<const uint4*>(fhm + s4 * CHANNELS);
            uint4 v5 = *reinterpret_cast<const uint4*>(fhm + s5 * CHANNELS);
            uint4 v6 = *reinterpret_cast<const uint4*>(fhm + s6 * CHANNELS);
            uint4 v7 = *reinterpret_cast<const uint4*>(fhm + s7 * CHANNELS);

            m0 = __hmax2(m0, __hmax2(hmax4(*(__half2*)&v0.x, *(__half2*)&v1.x,
                                           *(__half2*)&v2.x, *(__half2*)&v3.x),
                                     hmax4(*(__half2*)&v4.x, *(__half2*)&v5.x,
                                           *(__half2*)&v6.x, *(__half2*)&v7.x)));
            m1 = __hmax2(m1, __hmax2(hmax4(*(__half2*)&v0.y, *(__half2*)&v1.y,
                                           *(__half2*)&v2.y, *(__half2*)&v3.y),
                                     hmax4(*(__half2*)&v4.y, *(__half2*)&v5.y,
                                           *(__half2*)&v6.y, *(__half2*)&v7.y)));
            m2 = __hmax2(m2, __hmax2(hmax4(*(__half2*)&v0.z, *(__half2*)&v1.z,
                                           *(__half2*)&v2.z, *(__half2*)&v3.z),
                                     hmax4(*(__half2*)&v4.z, *(__half2*)&v5.z,
                                           *(__half2*)&v6.z, *(__half2*)&v7.z)));
            m3 = __hmax2(m3, __hmax2(hmax4(*(__half2*)&v0.w, *(__half2*)&v1.w,
                                           *(__half2*)&v2.w, *(__half2*)&v3.w),
                                     hmax4(*(__half2*)&v4.w, *(__half2*)&v5.w,
                                           *(__half2*)&v6.w, *(__half2*)&v7.w)));
        }
    }

    // Exactness guard: fold in any overflow edges targeting this point.
    int ovf = d_ovf_count;
    if (ovf > 0 && overflowed) {
        if (ovf > OVF_CAP) ovf = OVF_CAP;
        for (int j = 0; j < ovf; j++) {
            int e = d_ovf_list[j];
            int2 pr = __ldg(reinterpret_cast<const int2*>(idx) + e);
            if (pr.x == p) {
                const __half* fv = d_feat_h + pr.y * CHANNELS + c8;
                uint4 v = *reinterpret_cast<const uint4*>(fv);
                m0 = __hmax2(m0, *(__half2*)&v.x);
                m1 = __hmax2(m1, *(__half2*)&v.y);
                m2 = __hmax2(m2, *(__half2*)&v.z);
                m3 = __hmax2(m3, *(__half2*)&v.w);
            }
        }
    }

    // Convert to fp32 and store (two float4 = 32B per lane, coalesced).
    float2 f0 = __half22float2(m0);
    float2 f1 = __half22float2(m1);
    float2 f2 = __half22float2(m2);
    float2 f3 = __half22float2(m3);
    float4* op = reinterpret_cast<float4*>(out + p * CHANNELS + c8);
    op[0] = make_float4(f0.x, f0.y, f1.x, f1.y);
    op[1] = make_float4(f2.x, f2.y, f3.x, f3.y);

    // --- Self-clean epilogue (restore zero sentinels + counters) ---
    // All 8 lanes of point p live in the same warp; sync the warp so every
    // lane has finished reading the row before we zero it.
    __syncwarp();
    int lane8 = t & 7;
    int numq = (n + 7) >> 3;                      // consumed 16B quads (<=16)
    uint4 z = make_uint4(0, 0, 0, 0);
    unsigned short* bw = d_bucket + p * CAP;
    if (lane8 < numq)
        *reinterpret_cast<uint4*>(bw + lane8 * 8) = z;
    if (lane8 + 8 < numq)
        *reinterpret_cast<uint4*>(bw + (lane8 + 8) * 8) = z;
    if (lane8 < NREP) *cursor_ptr(lane8, p) = 0;  // lanes 0..3: one replica each
    if (threadIdx.x == 0) {
        __threadfence();
        int old = atomicAdd(&d_done, 1);
        if (old == gridDim.x - 1) {               // last block: everyone has
            d_ovf_count = 0;                      // already read d_ovf_count
            d_done = 0;
        }
    }
}

extern "C" void kernel_launch(void* const* d_in, const int* in_sizes, int n_in,
                              void* d_out, int out_size) {
    const float* feat = (const float*)d_in[0];   // [N_POINTS, 64] f32
    const int* idx = (const int*)d_in[1];        // [N_EDGES, 2] i32
    float* out = (float*)d_out;                  // [N_POINTS, 64] f32

    int n_edges = in_sizes[1] / 2;

    // K2: fused fp16 conversion + interleaved bucket build (1 edge/thread)
    int work = n_edges > CONV_TASKS ? n_edges : CONV_TASKS;
    bucket_kernel<<<(work + 255) / 256, 256>>>(idx, feat, n_edges);

    // K3: dense per-point max (8 lanes/point, contiguous interleaved row)
    segmax_kernel<<<(N_POINTS * 8) / K3_BLOCK, K3_BLOCK>>>(idx, out);
}

// round 16
// speedup vs baseline: 1.0899x; 1.0899x over previous
#include <cuda_runtime.h>
#include <cuda_fp16.h>
#include <math_constants.h>

#define N_POINTS 50000
#define CHANNELS 64
#define CAP 128           // bucket capacity per point; counts ~Poisson(32), max ~66
#define OVF_CAP (1 << 20) // overflow list capacity (expected usage: 0)

#define GRID 592          // 4 blocks/SM on 148+ SMs -> all co-resident (no deadlock)
#define BLOCK 256
#define CONV_TASKS (N_POINTS * 8)   // 400000 tasks x 8 floats
#define PB_TASKS (N_POINTS * 8)     // 8 lanes per point

// Static scratch (no allocations). All __device__ globals are zero-initialized
// at module load; the kernel restores every counter to zero before exiting, so
// the zero-invariant holds for every call and every graph replay.
__device__ int d_cursor[N_POINTS];
__device__ unsigned short d_bucket[N_POINTS * CAP]; // 12.8 MB; idx<50000 fits u16
__device__ __half d_feat_h[N_POINTS * CHANNELS];    // 6.4 MB fp16 feature mirror
__device__ int d_ovf_count;
__device__ int d_ovf_list[OVF_CAP];
__device__ unsigned int d_bar1;                     // grid barrier arrivals
__device__ unsigned int d_bar2;                     // exit arrivals (reset owner)

__device__ __forceinline__ __half2 hmax4(__half2 a, __half2 b, __half2 c, __half2 d) {
    return __hmax2(__hmax2(a, b), __hmax2(c, d));
}

static_assert((GRID * BLOCK) % 32 == 0 && PB_TASKS % 32 == 0,
              "phase-B warps must be fully in- or out-of-range");

// ---------------------------------------------------------------------------
// Fused persistent kernel.
//   Phase A: fp32->fp16 feature conversion + bucket build (R14's K2 body).
//   Software grid barrier (all blocks co-resident by construction).
//   Phase B: dense segment-max (R14's K3 body) + self-clean.
// Removes one kernel-launch boundary (~4us measured on this harness).
// ---------------------------------------------------------------------------
__global__ void __launch_bounds__(BLOCK, 4)
fused_kernel(const int* __restrict__ idx,
             const float* __restrict__ feat,
             float* __restrict__ out,
             int n_edges) {
    const int tid = blockIdx.x * BLOCK + threadIdx.x;
    const int stride = GRID * BLOCK;

    // ---- Phase A1: fp32 -> fp16 mirror (grid-stride) ----
    for (int t = tid; t < CONV_TASKS; t += stride) {
        const float4* src = reinterpret_cast<const float4*>(feat) + 2 * t;
        float4 a = __ldg(src);
        float4 b = __ldg(src + 1);
        uint4 h;
        *reinterpret_cast<__half2*>(&h.x) = __floats2half2_rn(a.x, a.y);
        *reinterpret_cast<__half2*>(&h.y) = __floats2half2_rn(a.z, a.w);
        *reinterpret_cast<__half2*>(&h.z) = __floats2half2_rn(b.x, b.y);
        *reinterpret_cast<__half2*>(&h.w) = __floats2half2_rn(b.z, b.w);
        *(reinterpret_cast<uint4*>(d_feat_h) + t) = h;
    }

    // ---- Phase A2: bucket build (grid-stride, 1 edge/iteration) ----
    for (int e = tid; e < n_edges; e += stride) {
        int2 pr = __ldg(reinterpret_cast<const int2*>(idx) + e);
        int pos = atomicAdd(&d_cursor[pr.x], 1);
        if (pos < CAP) {
            d_bucket[pr.x * CAP + pos] = (unsigned short)pr.y;
        } else {
            int op = atomicAdd(&d_ovf_count, 1);
            if (op < OVF_CAP) d_ovf_list[op] = e;
        }
    }

    // ---- Grid barrier (spin; safe: all GRID blocks are co-resident) ----
    __syncthreads();
    if (threadIdx.x == 0) {
        __threadfence();                       // publish phase-A writes
        atomicAdd(&d_bar1, 1u);
        volatile unsigned int* vb = &d_bar1;
        while (*vb < (unsigned int)GRID) { }
    }
    __syncthreads();
    __threadfence();                           // acquire phase-A writes

    // ---- Phase B: dense segment-max (grid-stride over 8 lanes/point) ----
    for (int t = tid; t < PB_TASKS; t += stride) {
        int p = t >> 3;
        int c8 = (t & 7) << 3;

        int cnt = d_cursor[p];
        if (cnt > CAP) cnt = CAP;
        const unsigned short* bkt = d_bucket + p * CAP;
        const __half* fh = d_feat_h + c8;

        const __half2 ninf = __float2half2_rn(-CUDART_INF_F);
        __half2 m0 = ninf, m1 = ninf, m2 = ninf, m3 = ninf;

        for (int i = 0; i < cnt; i += 8) {
            uint4 q = __ldg(reinterpret_cast<const uint4*>(bkt + i));  // 8 u16 idx
            int s0 = q.x & 0xFFFF, s1 = q.x >> 16;
            int s2 = q.y & 0xFFFF, s3 = q.y >> 16;
            int s4 = q.z & 0xFFFF, s5 = q.z >> 16;
            int s6 = q.w & 0xFFFF, s7 = q.w >> 16;

            int rem = cnt - i;          // >= 1
            if (rem < 8) {              // pad with s0 (valid, max-idempotent)
                if (rem < 2) s1 = s0;
                if (rem < 3) s2 = s0;
                if (rem < 4) s3 = s0;
                if (rem < 5) s4 = s0;
                if (rem < 6) s5 = s0;
                if (rem < 7) s6 = s0;
                s7 = s0;
            }

            uint4 v0 = *reinterpret_cast<const uint4*>(fh + s0 * CHANNELS);
            uint4 v1 = *reinterpret_cast<const uint4*>(fh + s1 * CHANNELS);
            uint4 v2 = *reinterpret_cast<const uint4*>(fh + s2 * CHANNELS);
            uint4 v3 = *reinterpret_cast<const uint4*>(fh + s3 * CHANNELS);
            uint4 v4 = *reinterpret_cast<const uint4*>(fh + s4 * CHANNELS);
            uint4 v5 = *reinterpret_cast<const uint4*>(fh + s5 * CHANNELS);
            uint4 v6 = *reinterpret_cast<const uint4*>(fh + s6 * CHANNELS);
            uint4 v7 = *reinterpret_cast<const uint4*>(fh + s7 * CHANNELS);

            m0 = __hmax2(m0, __hmax2(hmax4(*(__half2*)&v0.x, *(__half2*)&v1.x,
                                           *(__half2*)&v2.x, *(__half2*)&v3.x),
                                     hmax4(*(__half2*)&v4.x, *(__half2*)&v5.x,
                                           *(__half2*)&v6.x, *(__half2*)&v7.x)));
            m1 = __hmax2(m1, __hmax2(hmax4(*(__half2*)&v0.y, *(__half2*)&v1.y,
                                           *(__half2*)&v2.y, *(__half2*)&v3.y),
                                     hmax4(*(__half2*)&v4.y, *(__half2*)&v5.y,
                                           *(__half2*)&v6.y, *(__half2*)&v7.y)));
            m2 = __hmax2(m2, __hmax2(hmax4(*(__half2*)&v0.z, *(__half2*)&v1.z,
                                           *(__half2*)&v2.z, *(__half2*)&v3.z),
                                     hmax4(*(__half2*)&v4.z, *(__half2*)&v5.z,
                                           *(__half2*)&v6.z, *(__half2*)&v7.z)));
            m3 = __hmax2(m3, __hmax2(hmax4(*(__half2*)&v0.w, *(__half2*)&v1.w,
                                           *(__half2*)&v2.w, *(__half2*)&v3.w),
                                     hmax4(*(__half2*)&v4.w, *(__half2*)&v5.w,
                                           *(__half2*)&v6.w, *(__half2*)&v7.w)));
        }

        // Exactness guard: fold in any overflow edges targeting this point.
        int ovf = d_ovf_count;
        if (ovf > 0) {
            if (ovf > OVF_CAP) ovf = OVF_CAP;
            for (int j = 0; j < ovf; j++) {
                int e = d_ovf_list[j];
                int2 pr = __ldg(reinterpret_cast<const int2*>(idx) + e);
                if (pr.x == p) {
                    uint4 v = *reinterpret_cast<const uint4*>(fh + pr.y * CHANNELS);
                    m0 = __hmax2(m0, *(__half2*)&v.x);
                    m1 = __hmax2(m1, *(__half2*)&v.y);
                    m2 = __hmax2(m2, *(__half2*)&v.z);
                    m3 = __hmax2(m3, *(__half2*)&v.w);
                }
            }
        }

        float2 f0 = __half22float2(m0);
        float2 f1 = __half22float2(m1);
        float2 f2 = __half22float2(m2);
        float2 f3 = __half22float2(m3);
        float4* op = reinterpret_cast<float4*>(out + p * CHANNELS + c8);
        op[0] = make_float4(f0.x, f0.y, f1.x, f1.y);
        op[1] = make_float4(f2.x, f2.y, f3.x, f3.y);

        // Cursor self-clean. All 8 lanes of point p are in this warp and take
        // the same loop iteration (stride and bounds are warp-aligned).
        __syncwarp();
        if ((t & 7) == 0) d_cursor[p] = 0;
    }

    // ---- Exit: last block resets barrier + overflow counters ----
    __syncthreads();
    if (threadIdx.x == 0) {
        __threadfence();
        unsigned int old = atomicAdd(&d_bar2, 1u);
        if (old == (unsigned int)GRID - 1) {
            // Every block has passed the spin (it incremented d_bar2 only
            // after phase B) and has read d_ovf_count -> safe to reset.
            d_bar1 = 0;
            d_bar2 = 0;
            d_ovf_count = 0;
        }
    }
}

extern "C" void kernel_launch(void* const* d_in, const int* in_sizes, int n_in,
                              void* d_out, int out_size) {
    const float* feat = (const float*)d_in[0];   // [N_POINTS, 64] f32
    const int* idx = (const int*)d_in[1];        // [N_EDGES, 2] i32
    float* out = (float*)d_out;                  // [N_POINTS, 64] f32

    int n_edges = in_sizes[1] / 2;

    fused_kernel<<<GRID, BLOCK>>>(idx, feat, out, n_edges);
}